// round 1
// baseline (speedup 1.0000x reference)
#include <cuda_runtime.h>
#include <math.h>

#define T_TOK   2048      // tokens = 2*1024
#define DM      512       // d_model
#define E_EXP   64        // experts
#define TOPK    8
#define H_GATE  1024      // gate hidden (2D)
#define H_EXP   2048      // expert hidden (4D)
#define NPAIR   (T_TOK*TOPK)   // 16384 (token, expert) pairs

// ---------------- scratch (device globals; no runtime allocation) -----------
static __device__ float g_h[(size_t)T_TOK * H_GATE];        // gate hidden, 8 MiB
static __device__ float g_probs[T_TOK * E_EXP];             // softmax probs
static __device__ float g_topkw[T_TOK * TOPK];              // renormalized weights
static __device__ int   g_count[E_EXP];                     // tokens per expert
static __device__ int   g_list_t[E_EXP * T_TOK];            // token index per slot
static __device__ int   g_list_p[E_EXP * T_TOK];            // pair index per slot
static __device__ float g_hidden[(size_t)NPAIR * H_EXP];    // 128 MiB
static __device__ float g_ybuf[(size_t)NPAIR * DM];         // 32 MiB

// ---------------- generic gather/scatter SGEMM ------------------------------
// C[out(r), n] = act( sum_k A[in(r), k] * B[e][k, n] + bias[e][n] )
// BM=BN=128, BK=8, 256 threads, 8x8 microtile.
// ACT: 0 = none, 1 = relu, 2 = exact gelu
template<int ACT>
__global__ __launch_bounds__(256)
void sgemm_k(const float* __restrict__ A, int lda, int K,
             const float* __restrict__ Bbase, int N, size_t strideB,
             const float* __restrict__ biasBase, int strideBias,
             float* __restrict__ C, int ldc,
             const int* __restrict__ rowlist,   // may be null (identity)
             const int* __restrict__ outlist,   // may be null (identity)
             const int* __restrict__ cnts,      // may be null -> Mfixed
             int Mfixed)
{
    const int e = blockIdx.z;
    const int M = cnts ? cnts[e] : Mfixed;
    const int m0 = blockIdx.x * 128;
    if (m0 >= M) return;
    const int n0 = blockIdx.y * 128;

    const float* B  = Bbase + (size_t)e * strideB;
    const int*   rl = rowlist ? rowlist + e * T_TOK : nullptr;
    const int*   ol = outlist ? outlist + e * T_TOK : nullptr;

    __shared__ float As[8][128];   // [k][m] transposed
    __shared__ float Bs[8][128];   // [k][n]

    const int tid  = threadIdx.x;
    const int arow = tid >> 1;          // 0..127
    const int acol = (tid & 1) * 4;     // 0 or 4

    const float* aptr = nullptr;
    {
        int r = m0 + arow;
        if (r < M) {
            int src = rl ? rl[r] : r;
            aptr = A + (size_t)src * lda + acol;
        }
    }
    const float* bptr = B + (size_t)(tid >> 5) * N + n0 + (tid & 31) * 4;

    const int ty = tid >> 4;   // 0..15 -> row group
    const int tx = tid & 15;   // 0..15 -> col group

    float acc[8][8];
    #pragma unroll
    for (int i = 0; i < 8; i++)
        #pragma unroll
        for (int j = 0; j < 8; j++) acc[i][j] = 0.f;

    for (int k0 = 0; k0 < K; k0 += 8) {
        float4 av = make_float4(0.f, 0.f, 0.f, 0.f);
        if (aptr) av = *(const float4*)(aptr + k0);
        float4 bv = *(const float4*)(bptr + (size_t)k0 * N);

        As[acol + 0][arow] = av.x;
        As[acol + 1][arow] = av.y;
        As[acol + 2][arow] = av.z;
        As[acol + 3][arow] = av.w;
        *(float4*)&Bs[tid >> 5][(tid & 31) * 4] = bv;
        __syncthreads();

        #pragma unroll
        for (int kk = 0; kk < 8; kk++) {
            float rA[8], rB[8];
            *(float4*)&rA[0] = *(const float4*)&As[kk][ty * 8];
            *(float4*)&rA[4] = *(const float4*)&As[kk][ty * 8 + 4];
            *(float4*)&rB[0] = *(const float4*)&Bs[kk][tx * 8];
            *(float4*)&rB[4] = *(const float4*)&Bs[kk][tx * 8 + 4];
            #pragma unroll
            for (int i = 0; i < 8; i++)
                #pragma unroll
                for (int j = 0; j < 8; j++)
                    acc[i][j] = fmaf(rA[i], rB[j], acc[i][j]);
        }
        __syncthreads();
    }

    // epilogue
    float bv8[8];
    {
        const float* bias = biasBase ? biasBase + (size_t)e * strideBias + n0 + tx * 8
                                     : nullptr;
        #pragma unroll
        for (int j = 0; j < 8; j++) bv8[j] = bias ? bias[j] : 0.f;
    }
    #pragma unroll
    for (int i = 0; i < 8; i++) {
        int r = m0 + ty * 8 + i;
        if (r >= M) continue;
        int orow = ol ? ol[r] : r;
        float* cp = C + (size_t)orow * ldc + n0 + tx * 8;
        float v[8];
        #pragma unroll
        for (int j = 0; j < 8; j++) {
            float t = acc[i][j] + bv8[j];
            if (ACT == 1) t = fmaxf(t, 0.f);
            if (ACT == 2) t = 0.5f * t * (1.f + erff(t * 0.70710678118654752f));
            v[j] = t;
        }
        *(float4*)(cp)     = make_float4(v[0], v[1], v[2], v[3]);
        *(float4*)(cp + 4) = make_float4(v[4], v[5], v[6], v[7]);
    }
}

// ---------------- gating: logits + softmax + top-8 + routing ----------------
__global__ void gate_route_kernel(const float* __restrict__ h,
                                  const float* __restrict__ w2,
                                  const float* __restrict__ b2)
{
    __shared__ float hs[H_GATE];
    __shared__ float red[E_EXP];
    __shared__ int   ridx[E_EXP];
    __shared__ float pv[E_EXP];
    __shared__ float selw[TOPK];
    __shared__ int   seli[TOPK];

    const int t = blockIdx.x;
    const int tid = threadIdx.x;   // 64 threads; tid == expert id

    for (int i = tid; i < H_GATE; i += E_EXP) hs[i] = h[(size_t)t * H_GATE + i];
    __syncthreads();

    float acc = b2[tid];
    #pragma unroll 8
    for (int kk = 0; kk < H_GATE; kk++)
        acc = fmaf(hs[kk], w2[kk * E_EXP + tid], acc);

    // softmax over 64
    red[tid] = acc; __syncthreads();
    for (int s = 32; s > 0; s >>= 1) { if (tid < s) red[tid] = fmaxf(red[tid], red[tid + s]); __syncthreads(); }
    float m = red[0]; __syncthreads();
    float p = expf(acc - m);
    red[tid] = p; __syncthreads();
    for (int s = 32; s > 0; s >>= 1) { if (tid < s) red[tid] += red[tid + s]; __syncthreads(); }
    float sum = red[0]; __syncthreads();
    p /= sum;
    g_probs[t * E_EXP + tid] = p;

    // top-8 (iterative argmax, ties -> lower index like jax top_k)
    pv[tid] = p; __syncthreads();
    for (int k = 0; k < TOPK; k++) {
        red[tid] = pv[tid]; ridx[tid] = tid; __syncthreads();
        for (int s = 32; s > 0; s >>= 1) {
            if (tid < s) {
                if (red[tid + s] > red[tid] ||
                    (red[tid + s] == red[tid] && ridx[tid + s] < ridx[tid])) {
                    red[tid] = red[tid + s]; ridx[tid] = ridx[tid + s];
                }
            }
            __syncthreads();
        }
        if (tid == 0) { seli[k] = ridx[0]; selw[k] = red[0]; pv[ridx[0]] = -1.f; }
        __syncthreads();
    }

    if (tid == 0) {
        float s8 = 0.f;
        #pragma unroll
        for (int k = 0; k < TOPK; k++) s8 += selw[k];
        float inv = 1.f / s8;
        for (int k = 0; k < TOPK; k++) {
            int ee = seli[k];
            g_topkw[t * TOPK + k] = selw[k] * inv;
            int pos = atomicAdd(&g_count[ee], 1);
            g_list_t[ee * T_TOK + pos] = t;
            g_list_p[ee * T_TOK + pos] = t * TOPK + k;
        }
    }
}

// ---------------- load-balance loss ------------------------------------------
__global__ void lb_kernel(float* __restrict__ out, int out_size)
{
    __shared__ float red[E_EXP];
    const int e = threadIdx.x;
    float s = 0.f;
    for (int t = 0; t < T_TOK; t++) s += g_probs[t * E_EXP + e];
    float u = s / (float)T_TOK - 1.f / (float)E_EXP;
    red[e] = u * u; __syncthreads();
    for (int st = 32; st > 0; st >>= 1) { if (e < st) red[e] += red[e + st]; __syncthreads(); }
    if (e == 0 && out_size > T_TOK * DM)
        out[T_TOK * DM] = 0.01f * red[0] / (float)E_EXP;
}

// ---------------- weighted combine -------------------------------------------
__global__ void combine_kernel(float* __restrict__ out)
{
    const int t = blockIdx.x;
    for (int d = threadIdx.x; d < DM; d += 256) {
        float a = 0.f;
        #pragma unroll
        for (int k = 0; k < TOPK; k++)
            a = fmaf(g_topkw[t * TOPK + k],
                     g_ybuf[(size_t)(t * TOPK + k) * DM + d], a);
        out[(size_t)t * DM + d] = a;
    }
}

__global__ void zero_counts() { g_count[threadIdx.x] = 0; }

// ---------------- launch ------------------------------------------------------
extern "C" void kernel_launch(void* const* d_in, const int* in_sizes, int n_in,
                              void* d_out, int out_size)
{
    const float* x   = (const float*)d_in[0];
    const float* gw1 = (const float*)d_in[1];
    const float* gb1 = (const float*)d_in[2];
    const float* gw2 = (const float*)d_in[3];
    const float* gb2 = (const float*)d_in[4];
    const float* ew1 = (const float*)d_in[5];
    const float* eb1 = (const float*)d_in[6];
    const float* ew2 = (const float*)d_in[7];
    const float* eb2 = (const float*)d_in[8];
    float* out = (float*)d_out;

    float *ph, *phidden, *pybuf;
    int *pcnt, *plt, *plp;
    cudaGetSymbolAddress((void**)&ph,      g_h);
    cudaGetSymbolAddress((void**)&phidden, g_hidden);
    cudaGetSymbolAddress((void**)&pybuf,   g_ybuf);
    cudaGetSymbolAddress((void**)&pcnt,    g_count);
    cudaGetSymbolAddress((void**)&plt,     g_list_t);
    cudaGetSymbolAddress((void**)&plp,     g_list_p);

    zero_counts<<<1, E_EXP>>>();

    // gate layer 1: h = relu(x @ gw1 + gb1)   [2048,1024]
    sgemm_k<1><<<dim3(T_TOK/128, H_GATE/128, 1), 256>>>(
        x, DM, DM, gw1, H_GATE, 0, gb1, 0,
        ph, H_GATE, nullptr, nullptr, nullptr, T_TOK);

    // gate layer 2 + softmax + top-8 + routing
    gate_route_kernel<<<T_TOK, E_EXP>>>(ph, gw2, gb2);

    // load-balance scalar
    lb_kernel<<<1, E_EXP>>>(out, out_size);

    // grouped expert GEMM 1: hidden = gelu(x[list] @ ew1[e] + eb1[e])   [pairs, 2048]
    sgemm_k<2><<<dim3(T_TOK/128, H_EXP/128, E_EXP), 256>>>(
        x, DM, DM, ew1, H_EXP, (size_t)DM * H_EXP, eb1, H_EXP,
        phidden, H_EXP, plt, plp, pcnt, 0);

    // grouped expert GEMM 2: ybuf = hidden[list] @ ew2[e] + eb2[e]      [pairs, 512]
    sgemm_k<0><<<dim3(T_TOK/128, DM/128, E_EXP), 256>>>(
        phidden, H_EXP, H_EXP, ew2, DM, (size_t)H_EXP * DM, eb2, DM,
        pybuf, DM, plp, plp, pcnt, 0);

    // out[t] = sum_k w[t,k] * ybuf[t*8+k]
    combine_kernel<<<T_TOK, 256>>>(out);
}

// round 3
// speedup vs baseline: 1.8289x; 1.8289x over previous
#include <cuda_runtime.h>
#include <math.h>
#include <stdint.h>

#define T_TOK   2048
#define DM      512
#define E_EXP   64
#define TOPK    8
#define H_GATE  1024
#define H_EXP   2048
#define NPAIR   (T_TOK*TOPK)

// ---------------- scratch (device globals) ----------------------------------
static __device__ float g_h[(size_t)T_TOK * H_GATE];
static __device__ float g_probs[T_TOK * E_EXP];
static __device__ float g_topkw[T_TOK * TOPK];
static __device__ float g_usage[E_EXP];
static __device__ int   g_count[E_EXP];
static __device__ int   g_list_t[E_EXP * T_TOK];
static __device__ int   g_list_p[E_EXP * T_TOK];
static __device__ float g_hidden[(size_t)NPAIR * H_EXP];     // 128 MiB
static __device__ float g_ybuf[(size_t)NPAIR * DM];          // 32 MiB

// ---------------- helpers ----------------------------------------------------
__device__ __forceinline__ float f2tf(float f) {
    uint32_t r; asm("cvt.rna.tf32.f32 %0, %1;" : "=r"(r) : "f"(f));
    return __uint_as_float(r);
}
__device__ __forceinline__ void mma_tf32(float* c, const float* a, float b0, float b1) {
    asm volatile(
        "mma.sync.aligned.m16n8k8.row.col.f32.tf32.tf32.f32 "
        "{%0,%1,%2,%3}, {%4,%5,%6,%7}, {%8,%9}, {%0,%1,%2,%3};"
        : "+f"(c[0]), "+f"(c[1]), "+f"(c[2]), "+f"(c[3])
        : "r"(__float_as_uint(a[0])), "r"(__float_as_uint(a[1])),
          "r"(__float_as_uint(a[2])), "r"(__float_as_uint(a[3])),
          "r"(__float_as_uint(b0)), "r"(__float_as_uint(b1)));
}

// ---------------- tf32 mma.sync grouped GEMM --------------------------------
// C[out(r), n] = act( sum_k A[in(r), k] * B[e][k, n] + bias[e][n] )
// B is native [K][N] (N contiguous). Tile 128x128, BK=32, 8 warps (32x64 each).
// ACT: 0=none, 2=exact gelu.
template<int ACT>
__global__ __launch_bounds__(256, 1)
void mma_gemm(const float* __restrict__ A, int lda, int K,
              const float* __restrict__ Bbase, size_t strideB, int N,
              const float* __restrict__ biasBase, int strideBias,
              float* __restrict__ C, int ldc,
              const int* __restrict__ rowlist, const int* __restrict__ outlist,
              const int* __restrict__ cnts, int Mfixed)
{
    const int e  = blockIdx.z;
    const int M  = cnts ? cnts[e] : Mfixed;
    const int m0 = blockIdx.x * 128;
    if (m0 >= M) return;
    const int n0 = blockIdx.y * 128;

    extern __shared__ float sm[];                 // 16384 floats = 64KB
    float* sAb[2] = { sm,        sm + 4096 };     // 128 x 32 each (swizzled)
    float* sBb[2] = { sm + 8192, sm + 12288 };    // 32 x 128 each (swizzled)

    const int tid  = threadIdx.x;
    const int wid  = tid >> 5;
    const int lane = tid & 31;
    const int wy = wid & 3;            // row band (32 rows)
    const int wx = wid >> 2;           // col band (64 cols)
    const int g   = lane >> 2;         // 0..7
    const int tig = lane & 3;          // 0..3

    const float* B = Bbase + (size_t)e * strideB;
    const int* rl = rowlist ? rowlist + e * T_TOK : nullptr;
    const int* ol = outlist ? outlist + e * T_TOK : nullptr;

    // ---- global load assignments (4 float4 of A, 4 of B per thread) --------
    const float* aSrc[4]; int aSw[4];
    const float* bSrc[4]; int bSw[4];
    #pragma unroll
    for (int j = 0; j < 4; j++) {
        int idx = tid + j * 256;
        // A: row = idx>>3 (0..127), c4 = (idx&7)*4
        int ar = idx >> 3, ac = (idx & 7) * 4;
        aSw[j] = ar * 32 + (ac ^ ((ar & 7) << 2));
        int gm = m0 + ar;
        aSrc[j] = (gm < M) ? A + (size_t)(rl ? rl[gm] : gm) * lda + ac : nullptr;
        // B: k = idx>>5 (0..31), n4 = (idx&31)*4
        int bk = idx >> 5, bn = (idx & 31) * 4;
        bSw[j] = bk * 128 + (bn ^ ((bk & 3) << 3));
        bSrc[j] = B + (size_t)bk * N + n0 + bn;
    }

    float acc[2][8][4];
    #pragma unroll
    for (int fm = 0; fm < 2; fm++)
        #pragma unroll
        for (int fn = 0; fn < 8; fn++)
            #pragma unroll
            for (int q = 0; q < 4; q++) acc[fm][fn][q] = 0.f;

    const int NC = K / 32;
    float4 aReg[4], bReg[4];

    // prologue: load chunk 0, stage into buf 0
    #pragma unroll
    for (int j = 0; j < 4; j++) {
        aReg[j] = aSrc[j] ? *(const float4*)(aSrc[j]) : make_float4(0,0,0,0);
        bReg[j] = *(const float4*)(bSrc[j]);
    }
    #pragma unroll
    for (int j = 0; j < 4; j++) {
        *(float4*)&sAb[0][aSw[j]] = make_float4(f2tf(aReg[j].x), f2tf(aReg[j].y),
                                                f2tf(aReg[j].z), f2tf(aReg[j].w));
        *(float4*)&sBb[0][bSw[j]] = make_float4(f2tf(bReg[j].x), f2tf(bReg[j].y),
                                                f2tf(bReg[j].z), f2tf(bReg[j].w));
    }
    __syncthreads();

    for (int c = 0; c < NC; c++) {
        const int buf = c & 1;
        if (c + 1 < NC) {
            #pragma unroll
            for (int j = 0; j < 4; j++) {
                aReg[j] = aSrc[j] ? *(const float4*)(aSrc[j] + (size_t)(c + 1) * 32)
                                  : make_float4(0,0,0,0);
                bReg[j] = *(const float4*)(bSrc[j] + (size_t)(c + 1) * 32 * N);
            }
        }

        const float* sA = sAb[buf];
        const float* sB = sBb[buf];
        #pragma unroll
        for (int ks = 0; ks < 4; ks++) {
            float afr[2][4];
            #pragma unroll
            for (int fm = 0; fm < 2; fm++) {
                int rb = wy * 32 + fm * 16 + g;
                int c0 = (ks * 8 + tig)     ^ (g << 2);
                int c1 = (ks * 8 + tig + 4) ^ (g << 2);
                afr[fm][0] = sA[rb * 32 + c0];
                afr[fm][1] = sA[(rb + 8) * 32 + c0];
                afr[fm][2] = sA[rb * 32 + c1];
                afr[fm][3] = sA[(rb + 8) * 32 + c1];
            }
            #pragma unroll
            for (int fn = 0; fn < 8; fn++) {
                int col = wx * 64 + ((fn * 8) ^ (tig << 3)) + g;
                float b0 = sB[(ks * 8 + tig) * 128 + col];
                float b1 = sB[(ks * 8 + tig + 4) * 128 + col];
                mma_tf32(acc[0][fn], afr[0], b0, b1);
                mma_tf32(acc[1][fn], afr[1], b0, b1);
            }
        }

        if (c + 1 < NC) {
            float* dA = sAb[buf ^ 1];
            float* dB = sBb[buf ^ 1];
            #pragma unroll
            for (int j = 0; j < 4; j++) {
                *(float4*)&dA[aSw[j]] = make_float4(f2tf(aReg[j].x), f2tf(aReg[j].y),
                                                    f2tf(aReg[j].z), f2tf(aReg[j].w));
                *(float4*)&dB[bSw[j]] = make_float4(f2tf(bReg[j].x), f2tf(bReg[j].y),
                                                    f2tf(bReg[j].z), f2tf(bReg[j].w));
            }
        }
        __syncthreads();
    }

    // ---- epilogue -----------------------------------------------------------
    const float* bias = biasBase + (size_t)e * strideBias + n0;
    #pragma unroll
    for (int fm = 0; fm < 2; fm++) {
        int r0 = m0 + wy * 32 + fm * 16 + g;
        #pragma unroll
        for (int half = 0; half < 2; half++) {       // c0,c1 then c2,c3 (row+8)
            int row = r0 + half * 8;
            if (row >= M) continue;
            int orow = ol ? ol[row] : row;
            float* cp = C + (size_t)orow * ldc + n0;
            #pragma unroll
            for (int fn = 0; fn < 8; fn++) {
                int col = wx * 64 + fn * 8 + 2 * tig;
                float v0 = acc[fm][fn][half * 2 + 0] + bias[col];
                float v1 = acc[fm][fn][half * 2 + 1] + bias[col + 1];
                if (ACT == 2) {
                    v0 = 0.5f * v0 * (1.f + erff(v0 * 0.70710678118654752f));
                    v1 = 0.5f * v1 * (1.f + erff(v1 * 0.70710678118654752f));
                }
                *(float2*)(cp + col) = make_float2(v0, v1);
            }
        }
    }
}

// ---------------- fp32 SGEMM (gate layer 1 — precision-critical) ------------
__global__ __launch_bounds__(256)
void sgemm_relu(const float* __restrict__ A, int lda, int K,
                const float* __restrict__ B, int N,
                const float* __restrict__ bias,
                float* __restrict__ C, int ldc)
{
    const int m0 = blockIdx.x * 128;
    const int n0 = blockIdx.y * 128;

    __shared__ float As[8][128];
    __shared__ float Bs[8][128];

    const int tid  = threadIdx.x;
    const int arow = tid >> 1;
    const int acol = (tid & 1) * 4;
    const float* aptr = A + (size_t)(m0 + arow) * lda + acol;
    const float* bptr = B + (size_t)(tid >> 5) * N + n0 + (tid & 31) * 4;
    const int ty = tid >> 4, tx = tid & 15;

    float acc[8][8];
    #pragma unroll
    for (int i = 0; i < 8; i++)
        #pragma unroll
        for (int j = 0; j < 8; j++) acc[i][j] = 0.f;

    for (int k0 = 0; k0 < K; k0 += 8) {
        float4 av = *(const float4*)(aptr + k0);
        float4 bv = *(const float4*)(bptr + (size_t)k0 * N);
        As[acol + 0][arow] = av.x; As[acol + 1][arow] = av.y;
        As[acol + 2][arow] = av.z; As[acol + 3][arow] = av.w;
        *(float4*)&Bs[tid >> 5][(tid & 31) * 4] = bv;
        __syncthreads();
        #pragma unroll
        for (int kk = 0; kk < 8; kk++) {
            float rA[8], rB[8];
            *(float4*)&rA[0] = *(const float4*)&As[kk][ty * 8];
            *(float4*)&rA[4] = *(const float4*)&As[kk][ty * 8 + 4];
            *(float4*)&rB[0] = *(const float4*)&Bs[kk][tx * 8];
            *(float4*)&rB[4] = *(const float4*)&Bs[kk][tx * 8 + 4];
            #pragma unroll
            for (int i = 0; i < 8; i++)
                #pragma unroll
                for (int j = 0; j < 8; j++)
                    acc[i][j] = fmaf(rA[i], rB[j], acc[i][j]);
        }
        __syncthreads();
    }
    #pragma unroll
    for (int i = 0; i < 8; i++) {
        float* cp = C + (size_t)(m0 + ty * 8 + i) * ldc + n0 + tx * 8;
        float v[8];
        #pragma unroll
        for (int j = 0; j < 8; j++)
            v[j] = fmaxf(acc[i][j] + bias[n0 + tx * 8 + j], 0.f);
        *(float4*)(cp)     = make_float4(v[0], v[1], v[2], v[3]);
        *(float4*)(cp + 4) = make_float4(v[4], v[5], v[6], v[7]);
    }
}

// ---------------- gating: logits + softmax + top-8 + routing ----------------
__global__ void gate_route_kernel(const float* __restrict__ h,
                                  const float* __restrict__ w2,
                                  const float* __restrict__ b2)
{
    __shared__ float hs[H_GATE];
    __shared__ float red[E_EXP];
    __shared__ int   ridx[E_EXP];
    __shared__ float pv[E_EXP];
    __shared__ float selw[TOPK];
    __shared__ int   seli[TOPK];

    const int t = blockIdx.x;
    const int tid = threadIdx.x;

    for (int i = tid; i < H_GATE; i += E_EXP) hs[i] = h[(size_t)t * H_GATE + i];
    __syncthreads();

    float acc = b2[tid];
    #pragma unroll 8
    for (int kk = 0; kk < H_GATE; kk++)
        acc = fmaf(hs[kk], w2[kk * E_EXP + tid], acc);

    red[tid] = acc; __syncthreads();
    for (int s = 32; s > 0; s >>= 1) { if (tid < s) red[tid] = fmaxf(red[tid], red[tid + s]); __syncthreads(); }
    float m = red[0]; __syncthreads();
    float p = expf(acc - m);
    red[tid] = p; __syncthreads();
    for (int s = 32; s > 0; s >>= 1) { if (tid < s) red[tid] += red[tid + s]; __syncthreads(); }
    float sum = red[0]; __syncthreads();
    p /= sum;
    g_probs[t * E_EXP + tid] = p;

    pv[tid] = p; __syncthreads();
    for (int k = 0; k < TOPK; k++) {
        red[tid] = pv[tid]; ridx[tid] = tid; __syncthreads();
        for (int s = 32; s > 0; s >>= 1) {
            if (tid < s) {
                if (red[tid + s] > red[tid] ||
                    (red[tid + s] == red[tid] && ridx[tid + s] < ridx[tid])) {
                    red[tid] = red[tid + s]; ridx[tid] = ridx[tid + s];
                }
            }
            __syncthreads();
        }
        if (tid == 0) { seli[k] = ridx[0]; selw[k] = red[0]; pv[ridx[0]] = -1.f; }
        __syncthreads();
    }

    if (tid == 0) {
        float s8 = 0.f;
        #pragma unroll
        for (int k = 0; k < TOPK; k++) s8 += selw[k];
        float inv = 1.f / s8;
        for (int k = 0; k < TOPK; k++) {
            int ee = seli[k];
            g_topkw[t * TOPK + k] = selw[k] * inv;
            int pos = atomicAdd(&g_count[ee], 1);
            g_list_t[ee * T_TOK + pos] = t;
            g_list_p[ee * T_TOK + pos] = t * TOPK + k;
        }
    }
}

// ---------------- load-balance loss -------------------------------------------
__global__ void usage_kernel()
{
    __shared__ float red[128];
    const int e = blockIdx.x;
    float s = 0.f;
    for (int t = threadIdx.x; t < T_TOK; t += 128) s += g_probs[t * E_EXP + e];
    red[threadIdx.x] = s; __syncthreads();
    for (int st = 64; st > 0; st >>= 1) { if (threadIdx.x < st) red[threadIdx.x] += red[threadIdx.x + st]; __syncthreads(); }
    if (threadIdx.x == 0) {
        float u = red[0] / (float)T_TOK - 1.f / (float)E_EXP;
        g_usage[e] = u * u;
    }
}
__global__ void lb_final(float* __restrict__ out, int out_size)
{
    __shared__ float red[E_EXP];
    const int e = threadIdx.x;
    red[e] = g_usage[e]; __syncthreads();
    for (int st = 32; st > 0; st >>= 1) { if (e < st) red[e] += red[e + st]; __syncthreads(); }
    if (e == 0 && out_size > T_TOK * DM)
        out[T_TOK * DM] = 0.01f * red[0] / (float)E_EXP;
}

// ---------------- weighted combine -------------------------------------------
__global__ void combine_kernel(float* __restrict__ out)
{
    const int t = blockIdx.x;
    for (int d = threadIdx.x; d < DM; d += 256) {
        float a = 0.f;
        #pragma unroll
        for (int k = 0; k < TOPK; k++)
            a = fmaf(g_topkw[t * TOPK + k],
                     g_ybuf[(size_t)(t * TOPK + k) * DM + d], a);
        out[(size_t)t * DM + d] = a;
    }
}

__global__ void zero_counts() { g_count[threadIdx.x] = 0; }

// ---------------- launch ------------------------------------------------------
extern "C" void kernel_launch(void* const* d_in, const int* in_sizes, int n_in,
                              void* d_out, int out_size)
{
    const float* x   = (const float*)d_in[0];
    const float* gw1 = (const float*)d_in[1];
    const float* gb1 = (const float*)d_in[2];
    const float* gw2 = (const float*)d_in[3];
    const float* gb2 = (const float*)d_in[4];
    const float* ew1 = (const float*)d_in[5];
    const float* eb1 = (const float*)d_in[6];
    const float* ew2 = (const float*)d_in[7];
    const float* eb2 = (const float*)d_in[8];
    float* out = (float*)d_out;

    float *ph, *phidden, *pybuf;
    int *pcnt, *plt, *plp;
    cudaGetSymbolAddress((void**)&ph,      g_h);
    cudaGetSymbolAddress((void**)&phidden, g_hidden);
    cudaGetSymbolAddress((void**)&pybuf,   g_ybuf);
    cudaGetSymbolAddress((void**)&pcnt,    g_count);
    cudaGetSymbolAddress((void**)&plt,     g_list_t);
    cudaGetSymbolAddress((void**)&plp,     g_list_p);

    const int SMEM_DYN = 16384 * 4;   // 64 KB
    cudaFuncSetAttribute(mma_gemm<2>, cudaFuncAttributeMaxDynamicSharedMemorySize, SMEM_DYN);
    cudaFuncSetAttribute(mma_gemm<0>, cudaFuncAttributeMaxDynamicSharedMemorySize, SMEM_DYN);

    zero_counts<<<1, E_EXP>>>();

    // gate layer 1 (exact fp32 — routing depends on it)
    sgemm_relu<<<dim3(T_TOK/128, H_GATE/128), 256>>>(x, DM, DM, gw1, H_GATE, gb1, ph, H_GATE);

    gate_route_kernel<<<T_TOK, E_EXP>>>(ph, gw2, gb2);

    usage_kernel<<<E_EXP, 128>>>();
    lb_final<<<1, E_EXP>>>(out, out_size);

    // expert GEMM 1: hidden = gelu(x[list] @ ew1[e] + eb1[e])   (tf32 mma.sync)
    mma_gemm<2><<<dim3(T_TOK/128, H_EXP/128, E_EXP), 256, SMEM_DYN>>>(
        x, DM, DM, ew1, (size_t)DM * H_EXP, H_EXP, eb1, H_EXP,
        phidden, H_EXP, plt, plp, pcnt, 0);

    // expert GEMM 2: ybuf = hidden[list] @ ew2[e] + eb2[e]      (tf32 mma.sync)
    mma_gemm<0><<<dim3(T_TOK/128, DM/128, E_EXP), 256, SMEM_DYN>>>(
        phidden, H_EXP, H_EXP, ew2, (size_t)H_EXP * DM, DM, eb2, DM,
        pybuf, DM, plp, plp, pcnt, 0);

    combine_kernel<<<T_TOK, 256>>>(out);
}

// round 4
// speedup vs baseline: 2.8702x; 1.5693x over previous
#include <cuda_runtime.h>
#include <math.h>
#include <stdint.h>

#define T_TOK   2048
#define DM      512
#define E_EXP   64
#define TOPK    8
#define H_GATE  1024
#define H_EXP   2048
#define NPAIR   (T_TOK*TOPK)

// ---------------- scratch (device globals) ----------------------------------
static __device__ float g_h[(size_t)T_TOK * H_GATE];
static __device__ float g_probs[T_TOK * E_EXP];
static __device__ float g_topkw[T_TOK * TOPK];
static __device__ float g_usage[E_EXP];
static __device__ int   g_count[E_EXP];
static __device__ int   g_list_t[E_EXP * T_TOK];
static __device__ int   g_list_p[E_EXP * T_TOK];
static __device__ float g_hidden[(size_t)NPAIR * H_EXP];     // 128 MiB
static __device__ float g_ybuf[(size_t)NPAIR * DM];          // 32 MiB

// ---------------- helpers ----------------------------------------------------
__device__ __forceinline__ float f2tf(float f) {
    uint32_t r; asm("cvt.rna.tf32.f32 %0, %1;" : "=r"(r) : "f"(f));
    return __uint_as_float(r);
}
__device__ __forceinline__ uint32_t smem_u32(const void* p) {
    uint32_t a;
    asm("{ .reg .u64 t; cvta.to.shared.u64 t, %1; cvt.u32.u64 %0, t; }" : "=r"(a) : "l"(p));
    return a;
}
__device__ __forceinline__ void cp16(uint32_t dst, const void* src, int srcsize) {
    asm volatile("cp.async.cg.shared.global [%0], [%1], 16, %2;"
                 :: "r"(dst), "l"(src), "r"(srcsize) : "memory");
}
__device__ __forceinline__ void cp_commit() {
    asm volatile("cp.async.commit_group;" ::: "memory");
}
__device__ __forceinline__ void mma_tf32(float* c, const float* a, float b0, float b1) {
    asm volatile(
        "mma.sync.aligned.m16n8k8.row.col.f32.tf32.tf32.f32 "
        "{%0,%1,%2,%3}, {%4,%5,%6,%7}, {%8,%9}, {%0,%1,%2,%3};"
        : "+f"(c[0]), "+f"(c[1]), "+f"(c[2]), "+f"(c[3])
        : "r"(__float_as_uint(a[0])), "r"(__float_as_uint(a[1])),
          "r"(__float_as_uint(a[2])), "r"(__float_as_uint(a[3])),
          "r"(__float_as_uint(b0)), "r"(__float_as_uint(b1)));
}

// ---------------- tf32 mma.sync grouped GEMM, cp.async 3-stage --------------
// C[out(r), n] = act( sum_k A[in(r), k] * B[e][k, n] + bias[e][n] )
// B native [K][N]. Tile 128x128, BK=32, 8 warps (32x64 each). ACT: 0 none, 2 gelu.
template<int ACT>
__global__ __launch_bounds__(256)
void mma_gemm(const float* __restrict__ A, int lda, int K,
              const float* __restrict__ Bbase, size_t strideB, int N,
              const float* __restrict__ biasBase, int strideBias,
              float* __restrict__ C, int ldc,
              const int* __restrict__ rowlist, const int* __restrict__ outlist,
              const int* __restrict__ cnts, int Mfixed)
{
    const int e  = blockIdx.z;
    const int M  = cnts ? cnts[e] : Mfixed;
    const int m0 = blockIdx.x * 128;
    if (m0 >= M) return;
    const int n0 = blockIdx.y * 128;

    extern __shared__ float sm[];           // 3 stages x (4096 A + 4096 B) floats
    const uint32_t smBytes = smem_u32(sm);

    const int tid  = threadIdx.x;
    const int wid  = tid >> 5;
    const int lane = tid & 31;
    const int wy   = wid & 3;               // row band (32 rows)
    const int wx   = wid >> 2;              // col band (64 cols)
    const int g    = lane >> 2;
    const int tig  = lane & 3;

    const float* B = Bbase + (size_t)e * strideB;
    const int* rl = rowlist ? rowlist + e * T_TOK : nullptr;
    const int* ol = outlist ? outlist + e * T_TOK : nullptr;

    // ---- per-thread cp.async assignments (4 x 16B of A, 4 x 16B of B) ------
    const float* aSrc[4]; uint32_t aSw[4]; int aSz[4];
    const float* bSrc[4]; uint32_t bSw[4];
    #pragma unroll
    for (int j = 0; j < 4; j++) {
        int idx = tid + j * 256;
        int ar = idx >> 3, ac = (idx & 7) * 4;
        aSw[j] = (uint32_t)(ar * 32 + (ac ^ ((ar & 7) << 2))) * 4u;
        int gm = m0 + ar;
        if (gm < M) { aSrc[j] = A + (size_t)(rl ? rl[gm] : gm) * lda + ac; aSz[j] = 16; }
        else        { aSrc[j] = A;                                         aSz[j] = 0;  }
        int bk = idx >> 5, bn = (idx & 31) * 4;
        bSw[j] = (uint32_t)(bk * 128 + (bn ^ ((bk & 3) << 3))) * 4u;
        bSrc[j] = B + (size_t)bk * N + n0 + bn;
    }

    const int NC = K / 32;
    const size_t bStep = (size_t)32 * N;

    // stage s base (bytes): s*32768 ; A at +0, B at +16384
    #define ISSUE(cc) do { \
        uint32_t stA = smBytes + (uint32_t)((cc) % 3) * 32768u; \
        uint32_t stB = stA + 16384u; \
        _Pragma("unroll") \
        for (int j = 0; j < 4; j++) cp16(stA + aSw[j], aSrc[j] + (size_t)(cc) * 32, aSz[j]); \
        _Pragma("unroll") \
        for (int j = 0; j < 4; j++) cp16(stB + bSw[j], bSrc[j] + (size_t)(cc) * bStep, 16); \
        cp_commit(); \
    } while (0)

    ISSUE(0);
    if (NC > 1) ISSUE(1);

    float acc[2][8][4];
    #pragma unroll
    for (int fm = 0; fm < 2; fm++)
        #pragma unroll
        for (int fn = 0; fn < 8; fn++)
            #pragma unroll
            for (int q = 0; q < 4; q++) acc[fm][fn][q] = 0.f;

    for (int c = 0; c < NC; c++) {
        if (c + 1 < NC) asm volatile("cp.async.wait_group 1;" ::: "memory");
        else            asm volatile("cp.async.wait_group 0;" ::: "memory");
        __syncthreads();

        if (c + 2 < NC) ISSUE(c + 2);

        const float* sA = sm + (size_t)(c % 3) * 8192;
        const float* sB = sA + 4096;

        #pragma unroll
        for (int ks = 0; ks < 4; ks++) {
            float afr[2][4];
            #pragma unroll
            for (int fm = 0; fm < 2; fm++) {
                int rb = wy * 32 + fm * 16 + g;
                int c0 = (ks * 8 + tig)     ^ (g << 2);
                int c1 = (ks * 8 + tig + 4) ^ (g << 2);
                afr[fm][0] = f2tf(sA[rb * 32 + c0]);
                afr[fm][1] = f2tf(sA[(rb + 8) * 32 + c0]);
                afr[fm][2] = f2tf(sA[rb * 32 + c1]);
                afr[fm][3] = f2tf(sA[(rb + 8) * 32 + c1]);
            }
            #pragma unroll
            for (int fn = 0; fn < 8; fn++) {
                int col = wx * 64 + ((fn * 8) ^ (tig << 3)) + g;
                float b0 = f2tf(sB[(ks * 8 + tig) * 128 + col]);
                float b1 = f2tf(sB[(ks * 8 + tig + 4) * 128 + col]);
                mma_tf32(acc[0][fn], afr[0], b0, b1);
                mma_tf32(acc[1][fn], afr[1], b0, b1);
            }
        }
        __syncthreads();
    }
    #undef ISSUE

    // ---- epilogue -----------------------------------------------------------
    const float* bias = biasBase + (size_t)e * strideBias + n0;
    #pragma unroll
    for (int fm = 0; fm < 2; fm++) {
        int r0 = m0 + wy * 32 + fm * 16 + g;
        #pragma unroll
        for (int half = 0; half < 2; half++) {
            int row = r0 + half * 8;
            if (row >= M) continue;
            int orow = ol ? ol[row] : row;
            float* cp = C + (size_t)orow * ldc + n0;
            #pragma unroll
            for (int fn = 0; fn < 8; fn++) {
                int col = wx * 64 + fn * 8 + 2 * tig;
                float v0 = acc[fm][fn][half * 2 + 0] + bias[col];
                float v1 = acc[fm][fn][half * 2 + 1] + bias[col + 1];
                if (ACT == 2) {
                    v0 = 0.5f * v0 * (1.f + erff(v0 * 0.70710678118654752f));
                    v1 = 0.5f * v1 * (1.f + erff(v1 * 0.70710678118654752f));
                }
                *(float2*)(cp + col) = make_float2(v0, v1);
            }
        }
    }
}

// ---------------- fp32 SGEMM (gate layer 1 — precision-critical) ------------
__global__ __launch_bounds__(256)
void sgemm_relu(const float* __restrict__ A, int lda, int K,
                const float* __restrict__ B, int N,
                const float* __restrict__ bias,
                float* __restrict__ C, int ldc)
{
    const int m0 = blockIdx.x * 128;
    const int n0 = blockIdx.y * 128;

    __shared__ float As[8][128];
    __shared__ float Bs[8][128];

    const int tid  = threadIdx.x;
    const int arow = tid >> 1;
    const int acol = (tid & 1) * 4;
    const float* aptr = A + (size_t)(m0 + arow) * lda + acol;
    const float* bptr = B + (size_t)(tid >> 5) * N + n0 + (tid & 31) * 4;
    const int ty = tid >> 4, tx = tid & 15;

    float acc[8][8];
    #pragma unroll
    for (int i = 0; i < 8; i++)
        #pragma unroll
        for (int j = 0; j < 8; j++) acc[i][j] = 0.f;

    for (int k0 = 0; k0 < K; k0 += 8) {
        float4 av = *(const float4*)(aptr + k0);
        float4 bv = *(const float4*)(bptr + (size_t)k0 * N);
        As[acol + 0][arow] = av.x; As[acol + 1][arow] = av.y;
        As[acol + 2][arow] = av.z; As[acol + 3][arow] = av.w;
        *(float4*)&Bs[tid >> 5][(tid & 31) * 4] = bv;
        __syncthreads();
        #pragma unroll
        for (int kk = 0; kk < 8; kk++) {
            float rA[8], rB[8];
            *(float4*)&rA[0] = *(const float4*)&As[kk][ty * 8];
            *(float4*)&rA[4] = *(const float4*)&As[kk][ty * 8 + 4];
            *(float4*)&rB[0] = *(const float4*)&Bs[kk][tx * 8];
            *(float4*)&rB[4] = *(const float4*)&Bs[kk][tx * 8 + 4];
            #pragma unroll
            for (int i = 0; i < 8; i++)
                #pragma unroll
                for (int j = 0; j < 8; j++)
                    acc[i][j] = fmaf(rA[i], rB[j], acc[i][j]);
        }
        __syncthreads();
    }
    #pragma unroll
    for (int i = 0; i < 8; i++) {
        float* cp = C + (size_t)(m0 + ty * 8 + i) * ldc + n0 + tx * 8;
        float v[8];
        #pragma unroll
        for (int j = 0; j < 8; j++)
            v[j] = fmaxf(acc[i][j] + bias[n0 + tx * 8 + j], 0.f);
        *(float4*)(cp)     = make_float4(v[0], v[1], v[2], v[3]);
        *(float4*)(cp + 4) = make_float4(v[4], v[5], v[6], v[7]);
    }
}

// ---------------- gating: logits + softmax + top-8 + routing ----------------
__global__ void gate_route_kernel(const float* __restrict__ h,
                                  const float* __restrict__ w2,
                                  const float* __restrict__ b2)
{
    __shared__ float hs[H_GATE];
    __shared__ float red[E_EXP];
    __shared__ int   ridx[E_EXP];
    __shared__ float pv[E_EXP];
    __shared__ float selw[TOPK];
    __shared__ int   seli[TOPK];

    const int t = blockIdx.x;
    const int tid = threadIdx.x;

    for (int i = tid; i < H_GATE; i += E_EXP) hs[i] = h[(size_t)t * H_GATE + i];
    __syncthreads();

    float acc = b2[tid];
    #pragma unroll 8
    for (int kk = 0; kk < H_GATE; kk++)
        acc = fmaf(hs[kk], w2[kk * E_EXP + tid], acc);

    red[tid] = acc; __syncthreads();
    for (int s = 32; s > 0; s >>= 1) { if (tid < s) red[tid] = fmaxf(red[tid], red[tid + s]); __syncthreads(); }
    float m = red[0]; __syncthreads();
    float p = expf(acc - m);
    red[tid] = p; __syncthreads();
    for (int s = 32; s > 0; s >>= 1) { if (tid < s) red[tid] += red[tid + s]; __syncthreads(); }
    float sum = red[0]; __syncthreads();
    p /= sum;
    g_probs[t * E_EXP + tid] = p;

    pv[tid] = p; __syncthreads();
    for (int k = 0; k < TOPK; k++) {
        red[tid] = pv[tid]; ridx[tid] = tid; __syncthreads();
        for (int s = 32; s > 0; s >>= 1) {
            if (tid < s) {
                if (red[tid + s] > red[tid] ||
                    (red[tid + s] == red[tid] && ridx[tid + s] < ridx[tid])) {
                    red[tid] = red[tid + s]; ridx[tid] = ridx[tid + s];
                }
            }
            __syncthreads();
        }
        if (tid == 0) { seli[k] = ridx[0]; selw[k] = red[0]; pv[ridx[0]] = -1.f; }
        __syncthreads();
    }

    if (tid == 0) {
        float s8 = 0.f;
        #pragma unroll
        for (int k = 0; k < TOPK; k++) s8 += selw[k];
        float inv = 1.f / s8;
        for (int k = 0; k < TOPK; k++) {
            int ee = seli[k];
            g_topkw[t * TOPK + k] = selw[k] * inv;
            int pos = atomicAdd(&g_count[ee], 1);
            g_list_t[ee * T_TOK + pos] = t;
            g_list_p[ee * T_TOK + pos] = t * TOPK + k;
        }
    }
}

// ---------------- load-balance loss -------------------------------------------
__global__ void usage_kernel()
{
    __shared__ float red[128];
    const int e = blockIdx.x;
    float s = 0.f;
    for (int t = threadIdx.x; t < T_TOK; t += 128) s += g_probs[t * E_EXP + e];
    red[threadIdx.x] = s; __syncthreads();
    for (int st = 64; st > 0; st >>= 1) { if (threadIdx.x < st) red[threadIdx.x] += red[threadIdx.x + st]; __syncthreads(); }
    if (threadIdx.x == 0) {
        float u = red[0] / (float)T_TOK - 1.f / (float)E_EXP;
        g_usage[e] = u * u;
    }
}
__global__ void lb_final(float* __restrict__ out, int out_size)
{
    __shared__ float red[E_EXP];
    const int e = threadIdx.x;
    red[e] = g_usage[e]; __syncthreads();
    for (int st = 32; st > 0; st >>= 1) { if (e < st) red[e] += red[e + st]; __syncthreads(); }
    if (e == 0 && out_size > T_TOK * DM)
        out[T_TOK * DM] = 0.01f * red[0] / (float)E_EXP;
}

// ---------------- weighted combine -------------------------------------------
__global__ void combine_kernel(float* __restrict__ out)
{
    const int t = blockIdx.x;
    for (int d = threadIdx.x; d < DM; d += 256) {
        float a = 0.f;
        #pragma unroll
        for (int k = 0; k < TOPK; k++)
            a = fmaf(g_topkw[t * TOPK + k],
                     g_ybuf[(size_t)(t * TOPK + k) * DM + d], a);
        out[(size_t)t * DM + d] = a;
    }
}

__global__ void zero_counts() { g_count[threadIdx.x] = 0; }

// ---------------- launch ------------------------------------------------------
extern "C" void kernel_launch(void* const* d_in, const int* in_sizes, int n_in,
                              void* d_out, int out_size)
{
    const float* x   = (const float*)d_in[0];
    const float* gw1 = (const float*)d_in[1];
    const float* gb1 = (const float*)d_in[2];
    const float* gw2 = (const float*)d_in[3];
    const float* gb2 = (const float*)d_in[4];
    const float* ew1 = (const float*)d_in[5];
    const float* eb1 = (const float*)d_in[6];
    const float* ew2 = (const float*)d_in[7];
    const float* eb2 = (const float*)d_in[8];
    float* out = (float*)d_out;

    float *ph, *phidden, *pybuf;
    int *pcnt, *plt, *plp;
    cudaGetSymbolAddress((void**)&ph,      g_h);
    cudaGetSymbolAddress((void**)&phidden, g_hidden);
    cudaGetSymbolAddress((void**)&pybuf,   g_ybuf);
    cudaGetSymbolAddress((void**)&pcnt,    g_count);
    cudaGetSymbolAddress((void**)&plt,     g_list_t);
    cudaGetSymbolAddress((void**)&plp,     g_list_p);

    const int SMEM_DYN = 3 * 32768;   // 96 KB: 3 stages x (16KB A + 16KB B)
    cudaFuncSetAttribute(mma_gemm<2>, cudaFuncAttributeMaxDynamicSharedMemorySize, SMEM_DYN);
    cudaFuncSetAttribute(mma_gemm<0>, cudaFuncAttributeMaxDynamicSharedMemorySize, SMEM_DYN);

    zero_counts<<<1, E_EXP>>>();

    // gate layer 1 (exact fp32 — routing depends on it)
    sgemm_relu<<<dim3(T_TOK/128, H_GATE/128), 256>>>(x, DM, DM, gw1, H_GATE, gb1, ph, H_GATE);

    gate_route_kernel<<<T_TOK, E_EXP>>>(ph, gw2, gb2);

    usage_kernel<<<E_EXP, 128>>>();
    lb_final<<<1, E_EXP>>>(out, out_size);

    // expert GEMM 1: hidden = gelu(x[list] @ ew1[e] + eb1[e])   (tf32, pipelined)
    mma_gemm<2><<<dim3(T_TOK/128, H_EXP/128, E_EXP), 256, SMEM_DYN>>>(
        x, DM, DM, ew1, (size_t)DM * H_EXP, H_EXP, eb1, H_EXP,
        phidden, H_EXP, plt, plp, pcnt, 0);

    // expert GEMM 2: ybuf = hidden[list] @ ew2[e] + eb2[e]      (tf32, pipelined)
    mma_gemm<0><<<dim3(T_TOK/128, DM/128, E_EXP), 256, SMEM_DYN>>>(
        phidden, H_EXP, H_EXP, ew2, (size_t)H_EXP * DM, DM, eb2, DM,
        pybuf, DM, plp, plp, pcnt, 0);

    combine_kernel<<<T_TOK, 256>>>(out);
}

// round 5
// speedup vs baseline: 3.4721x; 1.2097x over previous
#include <cuda_runtime.h>
#include <cuda_fp16.h>
#include <math.h>
#include <stdint.h>

#define T_TOK   2048
#define DM      512
#define E_EXP   64
#define TOPK    8
#define H_GATE  1024
#define H_EXP   2048
#define NPAIR   (T_TOK*TOPK)

// ---------------- scratch (device globals) ----------------------------------
static __device__ float  g_h[(size_t)T_TOK * H_GATE];
static __device__ float  g_probs[T_TOK * E_EXP];
static __device__ float  g_topkw[T_TOK * TOPK];
static __device__ float  g_usage[E_EXP];
static __device__ int    g_count[E_EXP];
static __device__ int    g_list_t[E_EXP * T_TOK];
static __device__ int    g_list_p[E_EXP * T_TOK];
static __device__ __half g_hidden16[(size_t)NPAIR * H_EXP];  // 64 MiB
static __device__ float  g_ybuf[(size_t)NPAIR * DM];         // 32 MiB

// ---------------- helpers ----------------------------------------------------
__device__ __forceinline__ uint32_t smem_u32(const void* p) {
    uint32_t a;
    asm("{ .reg .u64 t; cvta.to.shared.u64 t, %1; cvt.u32.u64 %0, t; }" : "=r"(a) : "l"(p));
    return a;
}
__device__ __forceinline__ uint32_t packh(float lo, float hi) {
    uint32_t r;
    asm("cvt.rn.f16x2.f32 %0, %1, %2;" : "=r"(r) : "f"(hi), "f"(lo));
    return r;
}
__device__ __forceinline__ void cp16(uint32_t dst, const void* src, int srcsize) {
    asm volatile("cp.async.cg.shared.global [%0], [%1], 16, %2;"
                 :: "r"(dst), "l"(src), "r"(srcsize) : "memory");
}
__device__ __forceinline__ void cp_commit() {
    asm volatile("cp.async.commit_group;" ::: "memory");
}
__device__ __forceinline__ void mma_f16(float* c, const uint32_t* a, uint32_t b0, uint32_t b1) {
    asm volatile(
        "mma.sync.aligned.m16n8k16.row.col.f32.f16.f16.f32 "
        "{%0,%1,%2,%3}, {%4,%5,%6,%7}, {%8,%9}, {%0,%1,%2,%3};"
        : "+f"(c[0]), "+f"(c[1]), "+f"(c[2]), "+f"(c[3])
        : "r"(a[0]), "r"(a[1]), "r"(a[2]), "r"(a[3]), "r"(b0), "r"(b1));
}

// ---------------- fp16 mma.sync grouped GEMM, cp.async 3-stage ---------------
// C[out(r), n] = act( sum_k A[in(r), k] * B[e][k, n] + bias[e][n] )
// AT: float (cvt at fragment load) or __half (direct). OT: float or __half.
// B native fp32 [K][N]. Tile 128x128, BK=32, 8 warps (32x64). ACT: 0 none, 2 gelu.
template<typename AT, typename OT, int ACT>
__global__ __launch_bounds__(256)
void mma_gemm(const AT* __restrict__ A, int lda, int K,
              const float* __restrict__ Bbase, size_t strideB, int N,
              const float* __restrict__ biasBase, int strideBias,
              OT* __restrict__ C, int ldc,
              const int* __restrict__ rowlist, const int* __restrict__ outlist,
              const int* __restrict__ cnts, int Mfixed)
{
    constexpr bool A32 = (sizeof(AT) == 4);
    constexpr uint32_t ABYTES = A32 ? 16384u : 10240u;   // fp32: 128x32 swz; fp16: 128x40 pad
    constexpr uint32_t STAGE  = ABYTES + 16384u;         // + B 32x128 fp32 swz
    constexpr int NA = A32 ? 4 : 2;                      // A cp.async per thread

    const int e  = blockIdx.z;
    const int M  = cnts ? cnts[e] : Mfixed;
    const int m0 = blockIdx.x * 128;
    if (m0 >= M) return;
    const int n0 = blockIdx.y * 128;

    extern __shared__ char sm[];
    const uint32_t smBytes = smem_u32(sm);

    const int tid  = threadIdx.x;
    const int wid  = tid >> 5;
    const int lane = tid & 31;
    const int wy   = wid & 3;
    const int wx   = wid >> 2;
    const int g    = lane >> 2;
    const int tig  = lane & 3;

    const float* B = Bbase + (size_t)e * strideB;
    const int* rl = rowlist ? rowlist + e * T_TOK : nullptr;
    const int* ol = outlist ? outlist + e * T_TOK : nullptr;

    // ---- cp.async assignments ----------------------------------------------
    const AT* aSrc[NA]; uint32_t aOff[NA]; int aSz[NA];
    #pragma unroll
    for (int j = 0; j < NA; j++) {
        int idx = tid + j * 256;
        int ar, ac;
        if (A32) { ar = idx >> 3; ac = (idx & 7) * 4;
                   aOff[j] = (uint32_t)(ar * 32 + (ac ^ ((ar & 7) << 2))) * 4u; }
        else     { ar = idx >> 2; ac = (idx & 3) * 8;
                   aOff[j] = (uint32_t)ar * 80u + (uint32_t)(idx & 3) * 16u; }
        int gm = m0 + ar;
        if (gm < M) { aSrc[j] = A + (size_t)(rl ? rl[gm] : gm) * lda + ac; aSz[j] = 16; }
        else        { aSrc[j] = A;                                         aSz[j] = 0;  }
    }
    const float* bSrc[4]; uint32_t bOff[4];
    #pragma unroll
    for (int j = 0; j < 4; j++) {
        int idx = tid + j * 256;
        int bk = idx >> 5, bn = (idx & 31) * 4;
        bOff[j] = ABYTES + (uint32_t)(bk * 128 + (bn ^ ((bk & 7) << 2))) * 4u;
        bSrc[j] = B + (size_t)bk * N + n0 + bn;
    }

    const int NC = K / 32;
    const size_t bStep = (size_t)32 * N;

    #define ISSUE(cc) do { \
        uint32_t st = smBytes + (uint32_t)((cc) % 3) * STAGE; \
        _Pragma("unroll") \
        for (int j = 0; j < NA; j++) cp16(st + aOff[j], aSrc[j] + (size_t)(cc) * 32, aSz[j]); \
        _Pragma("unroll") \
        for (int j = 0; j < 4; j++) cp16(st + bOff[j], bSrc[j] + (size_t)(cc) * bStep, 16); \
        cp_commit(); \
    } while (0)

    ISSUE(0);
    if (NC > 1) ISSUE(1);

    float acc[2][8][4];
    #pragma unroll
    for (int fm = 0; fm < 2; fm++)
        #pragma unroll
        for (int fn = 0; fn < 8; fn++)
            #pragma unroll
            for (int q = 0; q < 4; q++) acc[fm][fn][q] = 0.f;

    for (int c = 0; c < NC; c++) {
        if (c + 1 < NC) asm volatile("cp.async.wait_group 1;" ::: "memory");
        else            asm volatile("cp.async.wait_group 0;" ::: "memory");
        __syncthreads();

        if (c + 2 < NC) ISSUE(c + 2);

        const char*   stg = sm + (size_t)(c % 3) * STAGE;
        const float*  sAf = (const float*)stg;
        const __half* sAh = (const __half*)stg;
        const float*  sBf = (const float*)(stg + ABYTES);

        #pragma unroll
        for (int ks = 0; ks < 2; ks++) {
            const int kb = ks * 16;
            const int c0 = kb + 2 * tig;
            uint32_t afr[2][4];
            #pragma unroll
            for (int fm = 0; fm < 2; fm++) {
                int r0 = wy * 32 + fm * 16 + g;
                if (A32) {
                    #pragma unroll
                    for (int q = 0; q < 4; q++) {
                        int r = r0 + (q & 1) * 8;
                        int cc = c0 + (q >> 1) * 8;
                        int off = r * 32 + (((cc & ~3) ^ ((r & 7) << 2)) | (cc & 3));
                        float2 v = *(const float2*)(sAf + off);
                        afr[fm][q] = packh(v.x, v.y);
                    }
                } else {
                    #pragma unroll
                    for (int q = 0; q < 4; q++) {
                        int r = r0 + (q & 1) * 8;
                        int cc = c0 + (q >> 1) * 8;
                        afr[fm][q] = *(const uint32_t*)(sAh + r * 40 + cc);
                    }
                }
            }
            #pragma unroll
            for (int fn = 0; fn < 8; fn++) {
                int n = wx * 64 + fn * 8 + g;
                int nsw_hi = n & ~3, nin = n & 3;
                int k0 = c0;
                float b00 = sBf[(k0    ) * 128 + ((nsw_hi ^ (((k0    ) & 7) << 2)) | nin)];
                float b01 = sBf[(k0 + 1) * 128 + ((nsw_hi ^ (((k0 + 1) & 7) << 2)) | nin)];
                float b10 = sBf[(k0 + 8) * 128 + ((nsw_hi ^ (((k0 + 8) & 7) << 2)) | nin)];
                float b11 = sBf[(k0 + 9) * 128 + ((nsw_hi ^ (((k0 + 9) & 7) << 2)) | nin)];
                uint32_t b0 = packh(b00, b01);
                uint32_t b1 = packh(b10, b11);
                mma_f16(acc[0][fn], afr[0], b0, b1);
                mma_f16(acc[1][fn], afr[1], b0, b1);
            }
        }
        __syncthreads();
    }
    #undef ISSUE

    // ---- epilogue -----------------------------------------------------------
    const float* bias = biasBase + (size_t)e * strideBias + n0;
    #pragma unroll
    for (int fm = 0; fm < 2; fm++) {
        int r0 = m0 + wy * 32 + fm * 16 + g;
        #pragma unroll
        for (int half = 0; half < 2; half++) {
            int row = r0 + half * 8;
            if (row >= M) continue;
            int orow = ol ? ol[row] : row;
            OT* cp = C + (size_t)orow * ldc + n0;
            #pragma unroll
            for (int fn = 0; fn < 8; fn++) {
                int col = wx * 64 + fn * 8 + 2 * tig;
                float v0 = acc[fm][fn][half * 2 + 0] + bias[col];
                float v1 = acc[fm][fn][half * 2 + 1] + bias[col + 1];
                if (ACT == 2) {
                    v0 = 0.5f * v0 * (1.f + erff(v0 * 0.70710678118654752f));
                    v1 = 0.5f * v1 * (1.f + erff(v1 * 0.70710678118654752f));
                }
                if (sizeof(OT) == 4) {
                    *(float2*)((float*)cp + col) = make_float2(v0, v1);
                } else {
                    *(uint32_t*)((__half*)cp + col) = packh(v0, v1);
                }
            }
        }
    }
}

// ---------------- fp32 SGEMM (gate layer 1 — precision-critical) ------------
__global__ __launch_bounds__(256)
void sgemm_relu(const float* __restrict__ A, int lda, int K,
                const float* __restrict__ B, int N,
                const float* __restrict__ bias,
                float* __restrict__ C, int ldc)
{
    const int m0 = blockIdx.x * 128;
    const int n0 = blockIdx.y * 128;

    __shared__ float As[8][128];
    __shared__ float Bs[8][128];

    const int tid  = threadIdx.x;
    const int arow = tid >> 1;
    const int acol = (tid & 1) * 4;
    const float* aptr = A + (size_t)(m0 + arow) * lda + acol;
    const float* bptr = B + (size_t)(tid >> 5) * N + n0 + (tid & 31) * 4;
    const int ty = tid >> 4, tx = tid & 15;

    float acc[8][8];
    #pragma unroll
    for (int i = 0; i < 8; i++)
        #pragma unroll
        for (int j = 0; j < 8; j++) acc[i][j] = 0.f;

    for (int k0 = 0; k0 < K; k0 += 8) {
        float4 av = *(const float4*)(aptr + k0);
        float4 bv = *(const float4*)(bptr + (size_t)k0 * N);
        As[acol + 0][arow] = av.x; As[acol + 1][arow] = av.y;
        As[acol + 2][arow] = av.z; As[acol + 3][arow] = av.w;
        *(float4*)&Bs[tid >> 5][(tid & 31) * 4] = bv;
        __syncthreads();
        #pragma unroll
        for (int kk = 0; kk < 8; kk++) {
            float rA[8], rB[8];
            *(float4*)&rA[0] = *(const float4*)&As[kk][ty * 8];
            *(float4*)&rA[4] = *(const float4*)&As[kk][ty * 8 + 4];
            *(float4*)&rB[0] = *(const float4*)&Bs[kk][tx * 8];
            *(float4*)&rB[4] = *(const float4*)&Bs[kk][tx * 8 + 4];
            #pragma unroll
            for (int i = 0; i < 8; i++)
                #pragma unroll
                for (int j = 0; j < 8; j++)
                    acc[i][j] = fmaf(rA[i], rB[j], acc[i][j]);
        }
        __syncthreads();
    }
    #pragma unroll
    for (int i = 0; i < 8; i++) {
        float* cp = C + (size_t)(m0 + ty * 8 + i) * ldc + n0 + tx * 8;
        float v[8];
        #pragma unroll
        for (int j = 0; j < 8; j++)
            v[j] = fmaxf(acc[i][j] + bias[n0 + tx * 8 + j], 0.f);
        *(float4*)(cp)     = make_float4(v[0], v[1], v[2], v[3]);
        *(float4*)(cp + 4) = make_float4(v[4], v[5], v[6], v[7]);
    }
}

// ---------------- gating: logits + softmax + top-8 + routing ----------------
__global__ void gate_route_kernel(const float* __restrict__ h,
                                  const float* __restrict__ w2,
                                  const float* __restrict__ b2)
{
    __shared__ float hs[H_GATE];
    __shared__ float red[E_EXP];
    __shared__ int   ridx[E_EXP];
    __shared__ float pv[E_EXP];
    __shared__ float selw[TOPK];
    __shared__ int   seli[TOPK];

    const int t = blockIdx.x;
    const int tid = threadIdx.x;

    for (int i = tid; i < H_GATE; i += E_EXP) hs[i] = h[(size_t)t * H_GATE + i];
    __syncthreads();

    float acc = b2[tid];
    #pragma unroll 8
    for (int kk = 0; kk < H_GATE; kk++)
        acc = fmaf(hs[kk], w2[kk * E_EXP + tid], acc);

    red[tid] = acc; __syncthreads();
    for (int s = 32; s > 0; s >>= 1) { if (tid < s) red[tid] = fmaxf(red[tid], red[tid + s]); __syncthreads(); }
    float m = red[0]; __syncthreads();
    float p = expf(acc - m);
    red[tid] = p; __syncthreads();
    for (int s = 32; s > 0; s >>= 1) { if (tid < s) red[tid] += red[tid + s]; __syncthreads(); }
    float sum = red[0]; __syncthreads();
    p /= sum;
    g_probs[t * E_EXP + tid] = p;

    pv[tid] = p; __syncthreads();
    for (int k = 0; k < TOPK; k++) {
        red[tid] = pv[tid]; ridx[tid] = tid; __syncthreads();
        for (int s = 32; s > 0; s >>= 1) {
            if (tid < s) {
                if (red[tid + s] > red[tid] ||
                    (red[tid + s] == red[tid] && ridx[tid + s] < ridx[tid])) {
                    red[tid] = red[tid + s]; ridx[tid] = ridx[tid + s];
                }
            }
            __syncthreads();
        }
        if (tid == 0) { seli[k] = ridx[0]; selw[k] = red[0]; pv[ridx[0]] = -1.f; }
        __syncthreads();
    }

    if (tid == 0) {
        float s8 = 0.f;
        #pragma unroll
        for (int k = 0; k < TOPK; k++) s8 += selw[k];
        float inv = 1.f / s8;
        for (int k = 0; k < TOPK; k++) {
            int ee = seli[k];
            g_topkw[t * TOPK + k] = selw[k] * inv;
            int pos = atomicAdd(&g_count[ee], 1);
            g_list_t[ee * T_TOK + pos] = t;
            g_list_p[ee * T_TOK + pos] = t * TOPK + k;
        }
    }
}

// ---------------- load-balance loss -------------------------------------------
__global__ void usage_kernel()
{
    __shared__ float red[128];
    const int e = blockIdx.x;
    float s = 0.f;
    for (int t = threadIdx.x; t < T_TOK; t += 128) s += g_probs[t * E_EXP + e];
    red[threadIdx.x] = s; __syncthreads();
    for (int st = 64; st > 0; st >>= 1) { if (threadIdx.x < st) red[threadIdx.x] += red[threadIdx.x + st]; __syncthreads(); }
    if (threadIdx.x == 0) {
        float u = red[0] / (float)T_TOK - 1.f / (float)E_EXP;
        g_usage[e] = u * u;
    }
}
__global__ void lb_final(float* __restrict__ out, int out_size)
{
    __shared__ float red[E_EXP];
    const int e = threadIdx.x;
    red[e] = g_usage[e]; __syncthreads();
    for (int st = 32; st > 0; st >>= 1) { if (e < st) red[e] += red[e + st]; __syncthreads(); }
    if (e == 0 && out_size > T_TOK * DM)
        out[T_TOK * DM] = 0.01f * red[0] / (float)E_EXP;
}

// ---------------- weighted combine -------------------------------------------
__global__ void combine_kernel(float* __restrict__ out)
{
    const int t = blockIdx.x;
    for (int d = threadIdx.x; d < DM; d += 256) {
        float a = 0.f;
        #pragma unroll
        for (int k = 0; k < TOPK; k++)
            a = fmaf(g_topkw[t * TOPK + k],
                     g_ybuf[(size_t)(t * TOPK + k) * DM + d], a);
        out[(size_t)t * DM + d] = a;
    }
}

__global__ void zero_counts() { g_count[threadIdx.x] = 0; }

// ---------------- launch ------------------------------------------------------
extern "C" void kernel_launch(void* const* d_in, const int* in_sizes, int n_in,
                              void* d_out, int out_size)
{
    const float* x   = (const float*)d_in[0];
    const float* gw1 = (const float*)d_in[1];
    const float* gb1 = (const float*)d_in[2];
    const float* gw2 = (const float*)d_in[3];
    const float* gb2 = (const float*)d_in[4];
    const float* ew1 = (const float*)d_in[5];
    const float* eb1 = (const float*)d_in[6];
    const float* ew2 = (const float*)d_in[7];
    const float* eb2 = (const float*)d_in[8];
    float* out = (float*)d_out;

    float *ph, *pybuf;
    __half* phid;
    int *pcnt, *plt, *plp;
    cudaGetSymbolAddress((void**)&ph,    g_h);
    cudaGetSymbolAddress((void**)&phid,  g_hidden16);
    cudaGetSymbolAddress((void**)&pybuf, g_ybuf);
    cudaGetSymbolAddress((void**)&pcnt,  g_count);
    cudaGetSymbolAddress((void**)&plt,   g_list_t);
    cudaGetSymbolAddress((void**)&plp,   g_list_p);

    const int SMEM1 = 3 * (16384 + 16384);   // A fp32 stages
    const int SMEM2 = 3 * (10240 + 16384);   // A fp16 stages
    cudaFuncSetAttribute((const void*)mma_gemm<float,  __half, 2>,
                         cudaFuncAttributeMaxDynamicSharedMemorySize, SMEM1);
    cudaFuncSetAttribute((const void*)mma_gemm<__half, float,  0>,
                         cudaFuncAttributeMaxDynamicSharedMemorySize, SMEM2);

    zero_counts<<<1, E_EXP>>>();

    // gate layer 1 (exact fp32 — routing depends on it)
    sgemm_relu<<<dim3(T_TOK/128, H_GATE/128), 256>>>(x, DM, DM, gw1, H_GATE, gb1, ph, H_GATE);

    gate_route_kernel<<<T_TOK, E_EXP>>>(ph, gw2, gb2);

    usage_kernel<<<E_EXP, 128>>>();
    lb_final<<<1, E_EXP>>>(out, out_size);

    // expert GEMM 1: hidden16 = gelu(x[list] @ ew1[e] + eb1[e])   (fp16 mma)
    mma_gemm<float, __half, 2><<<dim3(T_TOK/128, H_EXP/128, E_EXP), 256, SMEM1>>>(
        x, DM, DM, ew1, (size_t)DM * H_EXP, H_EXP, eb1, H_EXP,
        phid, H_EXP, plt, plp, pcnt, 0);

    // expert GEMM 2: ybuf = hidden16[list] @ ew2[e] + eb2[e]      (fp16 mma)
    mma_gemm<__half, float, 0><<<dim3(T_TOK/128, DM/128, E_EXP), 256, SMEM2>>>(
        phid, H_EXP, H_EXP, ew2, (size_t)H_EXP * DM, DM, eb2, DM,
        pybuf, DM, plp, plp, pcnt, 0);

    combine_kernel<<<T_TOK, 256>>>(out);
}